// round 15
// baseline (speedup 1.0000x reference)
#include <cuda_runtime.h>
#include <math.h>

#define H 512
#define HEADS 8
#define DK 64
#define NCLASS 4
#define VOCAB 5000
#define LW 32
#define NLEAF 20000
#define NPAR 20000
#define NTOT (NLEAF + NPAR)
#define DEG 4
#define NLAYER 5
#define MAXB 512
#define MAXL 512
#define MAXGRID 1024
#define NROWS 1536
#define RPB_MAX 8
#define BIGLVL 768
#define NCHUNK ((NPAR + 63) >> 6)   // 313 gate chunks

// ---- static device scratch ----
__device__ float g_Et[VOCAB * H];
__device__ float g_xe[NTOT * H];
__device__ float g_gz[NPAR * H];   // Wz@xe+bz -> z after B1
__device__ float g_gr[NPAR * H];   // Wr@xe+br -> mem*r after B1
__device__ float g_gh[NPAR * H];   // Wh@xe+bh
__device__ float g_mem[NPAR * H];
__device__ float g_ph[NPAR * H];
__device__ float g_pmax[MAXB * H];

__device__ int g_lvl[NPAR];
__device__ int g_lstart[MAXL + 2];
__device__ int g_nlev;
__device__ int g_order[NPAR];

__device__ volatile int g_arr[MAXGRID];     // wave barrier flags
__device__ int g_gate_next;                  // gate task counter
__device__ volatile int g_chunk_done[NCHUNK + 1];  // 12 subtasks per chunk

// ============================================================
__global__ __launch_bounds__(256) void prep_kernel(const float* __restrict__ E_bu) {
    __shared__ float tile[32][33];
    int v0 = blockIdx.x * 32;
    int h0 = blockIdx.y * 32;
    int tx = threadIdx.x & 31;
    int ty = threadIdx.x >> 5;
#pragma unroll
    for (int rr = 0; rr < 4; rr++) {
        int h = h0 + ty + rr * 8;
        int v = v0 + tx;
        if (v < VOCAB) tile[ty + rr * 8][tx] = E_bu[h * VOCAB + v];
    }
    __syncthreads();
#pragma unroll
    for (int rr = 0; rr < 4; rr++) {
        int v = v0 + ty + rr * 8;
        if (v < VOCAB) g_Et[v * H + h0 + tx] = tile[tx][ty + rr * 8];
    }
}

// ============================================================
__global__ __launch_bounds__(128) void xe_kernel(const float* __restrict__ xw,
                                                 const int* __restrict__ xi) {
    __shared__ float sw[LW];
    __shared__ int si[LW];
    int n = blockIdx.x;
    int t = threadIdx.x;
    if (t < LW) { sw[t] = xw[n * LW + t]; si[t] = xi[n * LW + t]; }
    __syncthreads();
    float4 acc = make_float4(0.f, 0.f, 0.f, 0.f);
#pragma unroll 8
    for (int l = 0; l < LW; l++) {
        float w = sw[l];
        const float4 e = *(const float4*)&g_Et[si[l] * H + t * 4];
        acc.x += w * e.x; acc.y += w * e.y; acc.z += w * e.z; acc.w += w * e.w;
    }
    *(float4*)&g_xe[n * H + t * 4] = acc;
}

// ============================================================
// Levels + bucketing (+ barrier/gate init). Single block, 1024 threads.
// ============================================================
extern __shared__ int s_dyn[];
__global__ void levels_kernel(const int* __restrict__ tree) {
    volatile int* lvl = s_dyn;
    int tid = threadIdx.x;
    int nt = blockDim.x;
    __shared__ int changed;
    __shared__ int s_maxl;
    __shared__ int cnt[MAXL + 1];

    if (tid < MAXGRID) g_arr[tid] = 0;
    if (tid <= NCHUNK) g_chunk_done[tid] = 0;
    if (tid == 0) g_gate_next = 0;

    for (int p = tid; p < NPAR; p += nt) lvl[p] = 1;
    if (tid == 0) s_maxl = 1;
    __syncthreads();

    for (int it = 0; it < 4096; it++) {
        if (tid == 0) changed = 0;
        __syncthreads();
        int ch = 0;
        for (int p = tid; p < NPAR; p += nt) {
            int4 t4 = ((const int4*)tree)[p];
            int m = 1;
            int c, v;
            c = t4.x; if (c >= NLEAF) { v = lvl[c - NLEAF] + 1; if (v > m) m = v; }
            c = t4.y; if (c >= NLEAF) { v = lvl[c - NLEAF] + 1; if (v > m) m = v; }
            c = t4.z; if (c >= NLEAF) { v = lvl[c - NLEAF] + 1; if (v > m) m = v; }
            c = t4.w; if (c >= NLEAF) { v = lvl[c - NLEAF] + 1; if (v > m) m = v; }
            if (m > lvl[p]) { lvl[p] = m; ch = 1; }
        }
        if (ch) changed = 1;
        __syncthreads();
        if (!changed) break;
    }

    for (int i = tid; i <= MAXL; i += nt) cnt[i] = 0;
    __syncthreads();
    int mymax = 1;
    for (int p = tid; p < NPAR; p += nt) {
        int l = lvl[p]; if (l > MAXL) l = MAXL;
        atomicAdd(&cnt[l], 1);
        if (l > mymax) mymax = l;
    }
    atomicMax(&s_maxl, mymax);
    __syncthreads();
    if (tid == 0) {
        int acc = 0;
        for (int l = 0; l <= MAXL; l++) { g_lstart[l] = acc; acc += cnt[l]; }
        g_lstart[MAXL + 1] = acc;
        g_nlev = s_maxl;
    }
    __syncthreads();
    for (int i = tid; i <= MAXL; i += nt) cnt[i] = g_lstart[i];
    __syncthreads();
    for (int p = tid; p < NPAR; p += nt) {
        int l = lvl[p]; if (l > MAXL) l = MAXL;
        int pos = atomicAdd(&cnt[l], 1);
        g_order[pos] = p;
        g_lvl[p] = l;
    }
}

// ============================================================
// Shared layouts
// ============================================================
struct alignas(16) ShSmall {
    float As[16][32];
    float Bs[16][64];
    int pidx[32];
};
struct alignas(16) ShBig {
    float As[32][64];
    float Bs[32][128];
    int pidx[64];
};
union alignas(16) ShU { ShSmall s; ShBig b; };

// wave barrier among nwave blocks (all-to-all flags, tight-poll fast path)
__device__ __forceinline__ void grid_sync2(int bid, int nwave, int& cnt) {
    cnt++;
    __threadfence();
    __syncthreads();
    if (threadIdx.x == 0) g_arr[bid] = cnt;
    for (int i = threadIdx.x; i < nwave; i += blockDim.x) {
        int tries = 0;
        while (g_arr[i] < cnt) {
            if (++tries > 64) __nanosleep(64);
        }
    }
    __threadfence();
    __syncthreads();
}

// wait until gate chunks [c0, c1] are fully written (12 subtasks each)
__device__ __forceinline__ void wait_chunks(int c0, int c1) {
    for (int c = c0 + threadIdx.x; c <= c1; c += blockDim.x) {
        int tries = 0;
        while (g_chunk_done[c] < 12) {
            if (++tries > 64) __nanosleep(64);
        }
    }
    __threadfence();
    __syncthreads();
}

// ---- GRU epilogue ----
template <int PHASE>
__device__ __forceinline__ void epilogue_elem(size_t pbase, int col, float v) {
    if (PHASE == 1) {
        if (col < H) {
            g_gz[pbase + col] = 1.0f / (1.0f + expf(-(v + g_gz[pbase + col])));
        } else {
            int c2 = col - H;
            float r = 1.0f / (1.0f + expf(-(v + g_gr[pbase + c2])));
            g_gr[pbase + c2] = g_mem[pbase + c2] * r;
        }
    } else {
        float cc = tanhf(v + g_gh[pbase + col]);
        float z = g_gz[pbase + col];
        float m = g_mem[pbase + col];
        g_ph[pbase + col] = z * m + (1.0f - z) * cc;
    }
}

// 32 x 64 output tile, full K=512 (mid levels).
template <int PHASE>
__device__ void gemm_tile(ShSmall* sb, int i0, int mtile, int jbase,
                          const float* __restrict__ Uz,
                          const float* __restrict__ Ur,
                          const float* __restrict__ Uh) {
    int tid = threadIdx.x;
    if (tid < 32) sb->pidx[tid] = g_order[i0 + ((tid < mtile) ? tid : 0)];
    __syncthreads();

    const float* Asrc = (PHASE == 1) ? g_mem : g_gr;
    const float* Bsrc;
    if (PHASE == 1) Bsrc = (jbase < H) ? (Uz + (size_t)jbase * H)
                                       : (Ur + (size_t)(jbase - H) * H);
    else            Bsrc = Uh + (size_t)jbase * H;

    float acc[2][4];
#pragma unroll
    for (int a = 0; a < 2; a++)
#pragma unroll
        for (int b = 0; b < 4; b++) acc[a][b] = 0.f;

    int tr = tid >> 4, tc = tid & 15;

    for (int k0 = 0; k0 < H; k0 += 16) {
        if (tid < 128) {
            int row = tid >> 2, kq = tid & 3;
            float4 f = *(const float4*)&Asrc[(size_t)sb->pidx[row] * H + k0 + kq * 4];
            sb->As[kq * 4 + 0][row] = f.x; sb->As[kq * 4 + 1][row] = f.y;
            sb->As[kq * 4 + 2][row] = f.z; sb->As[kq * 4 + 3][row] = f.w;
        }
        {
            int nn = tid >> 2, kq = tid & 3;
            float4 f = *(const float4*)&Bsrc[(size_t)nn * H + k0 + kq * 4];
            sb->Bs[kq * 4 + 0][nn] = f.x; sb->Bs[kq * 4 + 1][nn] = f.y;
            sb->Bs[kq * 4 + 2][nn] = f.z; sb->Bs[kq * 4 + 3][nn] = f.w;
        }
        __syncthreads();
#pragma unroll
        for (int kk = 0; kk < 16; kk++) {
            float2 ra = *(const float2*)&sb->As[kk][tr * 2];
            float4 rb = *(const float4*)&sb->Bs[kk][tc * 4];
            acc[0][0] += ra.x * rb.x; acc[0][1] += ra.x * rb.y;
            acc[0][2] += ra.x * rb.z; acc[0][3] += ra.x * rb.w;
            acc[1][0] += ra.y * rb.x; acc[1][1] += ra.y * rb.y;
            acc[1][2] += ra.y * rb.z; acc[1][3] += ra.y * rb.w;
        }
        __syncthreads();
    }

#pragma unroll
    for (int a = 0; a < 2; a++) {
        int i = tr * 2 + a;
        if (i >= mtile) continue;
        size_t pbase = (size_t)sb->pidx[i] * H;
#pragma unroll
        for (int b = 0; b < 4; b++)
            epilogue_elem<PHASE>(pbase, jbase + tc * 4 + b, acc[a][b]);
    }
    __syncthreads();
}

// 64 x 128 tile core (BK=32, register prefetch). MODE: 0=gate(Wx+b), 1/2=GRU phases.
template <int MODE>
__device__ void gemm_tile_big(ShBig* sb, int i0, int mtile, int jbase,
                              const float* __restrict__ Bmat,
                              const float* __restrict__ bias,
                              float* __restrict__ Cgate) {
    int tid = threadIdx.x;
    if (tid < 64) {
        int pid = g_order[i0 + ((tid < mtile) ? tid : 0)];
        sb->pidx[tid] = pid;
    }
    __syncthreads();

    const float* Asrc;
    if (MODE == 0) Asrc = g_xe + (size_t)NLEAF * H;
    else if (MODE == 1) Asrc = g_mem;
    else Asrc = g_gr;
    const float* Bsrc = Bmat;   // caller pre-offsets to jbase row

    float acc[4][8];
#pragma unroll
    for (int a = 0; a < 4; a++)
#pragma unroll
        for (int b = 0; b < 8; b++) acc[a][b] = 0.f;

    int tr = tid >> 4, tc = tid & 15;

    int kq = tid & 7;
    int arow0 = tid >> 3;
    int arow1 = arow0 + 32;
    const float* aptr0 = &Asrc[(size_t)sb->pidx[arow0] * H + kq * 4];
    const float* aptr1 = &Asrc[(size_t)sb->pidx[arow1] * H + kq * 4];
    const float* bptr0 = &Bsrc[(size_t)arow0 * H + kq * 4];
    const float* bptr1 = &Bsrc[(size_t)(arow0 + 32) * H + kq * 4];
    const float* bptr2 = &Bsrc[(size_t)(arow0 + 64) * H + kq * 4];
    const float* bptr3 = &Bsrc[(size_t)(arow0 + 96) * H + kq * 4];

    float4 rA0 = *(const float4*)aptr0;
    float4 rA1 = *(const float4*)aptr1;
    float4 rB0 = *(const float4*)bptr0;
    float4 rB1 = *(const float4*)bptr1;
    float4 rB2 = *(const float4*)bptr2;
    float4 rB3 = *(const float4*)bptr3;

    for (int c = 0; c < 16; c++) {
        __syncthreads();
        sb->As[kq * 4 + 0][arow0] = rA0.x; sb->As[kq * 4 + 1][arow0] = rA0.y;
        sb->As[kq * 4 + 2][arow0] = rA0.z; sb->As[kq * 4 + 3][arow0] = rA0.w;
        sb->As[kq * 4 + 0][arow1] = rA1.x; sb->As[kq * 4 + 1][arow1] = rA1.y;
        sb->As[kq * 4 + 2][arow1] = rA1.z; sb->As[kq * 4 + 3][arow1] = rA1.w;
        sb->Bs[kq * 4 + 0][arow0] = rB0.x; sb->Bs[kq * 4 + 1][arow0] = rB0.y;
        sb->Bs[kq * 4 + 2][arow0] = rB0.z; sb->Bs[kq * 4 + 3][arow0] = rB0.w;
        sb->Bs[kq * 4 + 0][arow0 + 32] = rB1.x; sb->Bs[kq * 4 + 1][arow0 + 32] = rB1.y;
        sb->Bs[kq * 4 + 2][arow0 + 32] = rB1.z; sb->Bs[kq * 4 + 3][arow0 + 32] = rB1.w;
        sb->Bs[kq * 4 + 0][arow0 + 64] = rB2.x; sb->Bs[kq * 4 + 1][arow0 + 64] = rB2.y;
        sb->Bs[kq * 4 + 2][arow0 + 64] = rB2.z; sb->Bs[kq * 4 + 3][arow0 + 64] = rB2.w;
        sb->Bs[kq * 4 + 0][arow0 + 96] = rB3.x; sb->Bs[kq * 4 + 1][arow0 + 96] = rB3.y;
        sb->Bs[kq * 4 + 2][arow0 + 96] = rB3.z; sb->Bs[kq * 4 + 3][arow0 + 96] = rB3.w;
        __syncthreads();
        if (c < 15) {
            int off = (c + 1) * 32;
            rA0 = *(const float4*)(aptr0 + off);
            rA1 = *(const float4*)(aptr1 + off);
            rB0 = *(const float4*)(bptr0 + off);
            rB1 = *(const float4*)(bptr1 + off);
            rB2 = *(const float4*)(bptr2 + off);
            rB3 = *(const float4*)(bptr3 + off);
        }
#pragma unroll
        for (int kk = 0; kk < 32; kk++) {
            float4 ra = *(const float4*)&sb->As[kk][tr * 4];
            float4 rb0 = *(const float4*)&sb->Bs[kk][tc * 8];
            float4 rb1 = *(const float4*)&sb->Bs[kk][tc * 8 + 4];
            float rav[4] = {ra.x, ra.y, ra.z, ra.w};
            float rbv[8] = {rb0.x, rb0.y, rb0.z, rb0.w, rb1.x, rb1.y, rb1.z, rb1.w};
#pragma unroll
            for (int a = 0; a < 4; a++)
#pragma unroll
                for (int b = 0; b < 8; b++) acc[a][b] += rav[a] * rbv[b];
        }
    }

#pragma unroll
    for (int a = 0; a < 4; a++) {
        int i = tr * 4 + a;
        if (i >= mtile) continue;
        size_t pbase = (size_t)sb->pidx[i] * H;
#pragma unroll
        for (int b = 0; b < 8; b++) {
            int col = jbase + tc * 8 + b;
            if (MODE == 0) Cgate[pbase + col] = acc[a][b] + bias[col];
            else epilogue_elem<MODE>(pbase, col, acc[a][b]);
        }
    }
    __syncthreads();
}

// ============================================================
// Warp-level attention: one warp handles (parent p, 2 heads).
// ============================================================
__device__ __forceinline__ void warp_attn2(int p, int hpair, int lane,
                                           const int* __restrict__ tree) {
    int4 t4 = ((const int4*)tree)[p];
    int carr[DEG] = {t4.x, t4.y, t4.z, t4.w};
    int cidx[DEG];
    int nc = 0;
#pragma unroll
    for (int j = 0; j < DEG; j++) {
        int c = carr[j];
        if (c > -1) cidx[nc++] = c;
    }

    int hd = hpair * 2 + (lane >> 4);
    int w = lane & 15;
    int off = hd * DK + w * 4;

    float4 cur[DEG];
#pragma unroll
    for (int q = 0; q < DEG; q++) {
        if (q < nc) {
            int c = cidx[q];
            const float* src = (c < NLEAF) ? &g_xe[(size_t)c * H]
                                           : &g_ph[(size_t)(c - NLEAF) * H];
            cur[q] = *(const float4*)&src[off];
        } else {
            cur[q] = make_float4(0.f, 0.f, 0.f, 0.f);
        }
    }

#pragma unroll
    for (int layer = 0; layer < NLAYER; layer++) {
        float sc[DEG][DEG];
#pragma unroll
        for (int q = 0; q < DEG; q++) {
#pragma unroll
            for (int k = 0; k <= q; k++) {
                float s = cur[q].x * cur[k].x + cur[q].y * cur[k].y
                        + cur[q].z * cur[k].z + cur[q].w * cur[k].w;
#pragma unroll
                for (int o = 8; o > 0; o >>= 1)
                    s += __shfl_xor_sync(0xffffffffu, s, o);
                s *= 0.125f;
                sc[q][k] = s;
                sc[k][q] = s;
            }
        }
        float4 nxt[DEG];
#pragma unroll
        for (int q = 0; q < DEG; q++) {
            float m = -1e30f;
#pragma unroll
            for (int k = 0; k < DEG; k++) {
                float v = (k < nc) ? sc[q][k] : -1e30f;
                m = fmaxf(m, v);
            }
            float pk[DEG];
            float ssum = 0.f;
#pragma unroll
            for (int k = 0; k < DEG; k++) {
                float e = (k < nc) ? __expf(sc[q][k] - m) : 0.f;
                pk[k] = e;
                ssum += e;
            }
            float inv = 1.0f / ssum;
            float4 o = make_float4(0.f, 0.f, 0.f, 0.f);
#pragma unroll
            for (int k = 0; k < DEG; k++) {
                float wk = pk[k] * inv;
                o.x += wk * cur[k].x;
                o.y += wk * cur[k].y;
                o.z += wk * cur[k].z;
                o.w += wk * cur[k].w;
            }
            nxt[q] = o;
        }
#pragma unroll
        for (int q = 0; q < DEG; q++) cur[q] = nxt[q];
    }

    float4 mm = make_float4(0.f, 0.f, 0.f, 0.f);
#pragma unroll
    for (int q = 0; q < DEG; q++) {
        if (q < nc) {
            mm.x += cur[q].x; mm.y += cur[q].y;
            mm.z += cur[q].z; mm.w += cur[q].w;
        }
    }
    float invn = 1.0f / (float)nc;
    mm.x *= invn; mm.y *= invn; mm.z *= invn; mm.w *= invn;
    *(float4*)&g_mem[(size_t)p * H + off] = mm;
}

// ============================================================
// Fused persistent kernel: blocks [0,nwave) = wave, [nwave,grid) = gate GEMM
// ============================================================
__global__ __launch_bounds__(256) void wave_kernel(const int* __restrict__ tree,
                                                   const float* __restrict__ Uz,
                                                   const float* __restrict__ Ur,
                                                   const float* __restrict__ Uh,
                                                   const float* __restrict__ Wz,
                                                   const float* __restrict__ Wr,
                                                   const float* __restrict__ Wh,
                                                   const float* __restrict__ bz,
                                                   const float* __restrict__ br,
                                                   const float* __restrict__ bh,
                                                   int nwave, int small_thresh) {
    __shared__ ShU sh;
    __shared__ __align__(16) float uRows[RPB_MAX][H];
    __shared__ int s_task;
    int tid = threadIdx.x;
    int bid = blockIdx.x;
    int wid = tid >> 5, lane = tid & 31;

    // ======== GATE BLOCKS ========
    if (bid >= nwave) {
        while (true) {
            if (tid == 0) s_task = atomicAdd(&g_gate_next, 1);
            __syncthreads();
            int t = s_task;
            if (t >= NCHUNK * 12) break;
            int c = t / 12;
            int sub = t - c * 12;
            int mat = sub >> 2;
            int j = sub & 3;
            int i0 = c * 64;
            int mtile = NPAR - i0; if (mtile > 64) mtile = 64;
            const float* W = (mat == 0) ? Wz : (mat == 1) ? Wr : Wh;
            const float* bias = (mat == 0) ? bz : (mat == 1) ? br : bh;
            float* C = (mat == 0) ? g_gz : (mat == 1) ? g_gr : g_gh;
            gemm_tile_big<0>(&sh.b, i0, mtile, j * 128, W + (size_t)j * 128 * H,
                             bias, C);
            __threadfence();
            __syncthreads();
            if (tid == 0) atomicAdd((int*)&g_chunk_done[c], 1);
            __syncthreads();
        }
        return;
    }

    // ======== WAVE BLOCKS ========
    int nb = nwave;
    int nlev = g_nlev;
    int cnt = 0;

    int rpb = (NROWS + nb - 1) / nb;
    if (rpb > RPB_MAX) rpb = RPB_MAX;
    int myrow0 = bid * rpb;
    int mynrows = NROWS - myrow0;
    if (mynrows < 0) mynrows = 0;
    if (mynrows > rpb) mynrows = rpb;

    for (int rr = 0; rr < mynrows; rr++) {
        int R = myrow0 + rr;
        const float* src = (R < H) ? &Uz[(size_t)R * H]
                         : (R < 2 * H) ? &Ur[(size_t)(R - H) * H]
                         : &Uh[(size_t)(R - 2 * H) * H];
        if (tid < 128) ((float4*)uRows[rr])[tid] = ((const float4*)src)[tid];
    }
    __syncthreads();

    int gw = bid * 8 + wid;
    int ngw = nb * 8;

    for (int l = 1; l <= nlev; l++) {
        int ls = g_lstart[l];
        int le = g_lstart[l + 1];
        int Nl = le - ls;

        // ---- Phase A ----
        {
            int ntask = Nl * 4;
            for (int t = gw; t < ntask; t += ngw) {
                int pi = t >> 2;
                int hpair = t & 3;
                warp_attn2(g_order[ls + pi], hpair, lane, tree);
            }
        }
        grid_sync2(bid, nb, cnt);

        if (Nl <= small_thresh) {
            // ---- small-level GEMV path ----
            wait_chunks(ls >> 6, (le - 1) >> 6);
            {
                int nzr = 0;
                int zr_rr[RPB_MAX];
                for (int rr = 0; rr < mynrows; rr++)
                    if (myrow0 + rr < 2 * H) zr_rr[nzr++] = rr;
                int ntask = nzr * Nl;
                for (int t = wid; t < ntask; t += 8) {
                    int ri = t / Nl;
                    int pi = t - ri * Nl;
                    int rr = zr_rr[ri];
                    int R = myrow0 + rr;
                    int p = g_order[ls + pi];
                    const float* mem = &g_mem[(size_t)p * H];
                    float s = 0.f;
#pragma unroll
                    for (int j = 0; j < 4; j++) {
                        int k = 4 * (lane + 32 * j);
                        float4 u = *(const float4*)&uRows[rr][k];
                        float4 m = *(const float4*)&mem[k];
                        s += u.x * m.x + u.y * m.y + u.z * m.z + u.w * m.w;
                    }
#pragma unroll
                    for (int o = 16; o > 0; o >>= 1) s += __shfl_down_sync(0xffffffffu, s, o);
                    if (lane == 0) {
                        if (R < H) {
                            size_t a = (size_t)p * H + R;
                            g_gz[a] = 1.0f / (1.0f + expf(-(s + g_gz[a])));
                        } else {
                            int r2 = R - H;
                            size_t a = (size_t)p * H + r2;
                            float r = 1.0f / (1.0f + expf(-(s + g_gr[a])));
                            g_gr[a] = mem[r2] * r;
                        }
                    }
                }
            }
            grid_sync2(bid, nb, cnt);

            {
                int ncr = 0;
                int c_rr[RPB_MAX];
                for (int rr = 0; rr < mynrows; rr++)
                    if (myrow0 + rr >= 2 * H) c_rr[ncr++] = rr;
                int ntask = ncr * Nl;
                for (int t = wid; t < ntask; t += 8) {
                    int ri = t / Nl;
                    int pi = t - ri * Nl;
                    int rr = c_rr[ri];
                    int row = myrow0 + rr - 2 * H;
                    int p = g_order[ls + pi];
                    const float* av = &g_gr[(size_t)p * H];
                    float s = 0.f;
#pragma unroll
                    for (int j = 0; j < 4; j++) {
                        int k = 4 * (lane + 32 * j);
                        float4 u = *(const float4*)&uRows[rr][k];
                        float4 m = *(const float4*)&av[k];
                        s += u.x * m.x + u.y * m.y + u.z * m.z + u.w * m.w;
                    }
#pragma unroll
                    for (int o = 16; o > 0; o >>= 1) s += __shfl_down_sync(0xffffffffu, s, o);
                    if (lane == 0) {
                        size_t a = (size_t)p * H + row;
                        float cc = tanhf(s + g_gh[a]);
                        float z = g_gz[a];
                        float m = g_mem[a];
                        g_ph[a] = z * m + (1.0f - z) * cc;
                    }
                }
            }
            grid_sync2(bid, nb, cnt);
        } else if (Nl >= BIGLVL) {
            // ---- big-level 64x128 tile path ----
            int pt64 = (Nl + 63) >> 6;
            int ntiles = pt64 * 8;
            for (int t = bid; t < ntiles; t += nb) {
                int pt = t >> 3;
                int jb = (t & 7) * 128;
                int i0 = ls + pt * 64;
                int mtile = Nl - pt * 64; if (mtile > 64) mtile = 64;
                wait_chunks(i0 >> 6, (i0 + mtile - 1) >> 6);
                const float* B = (jb < H) ? (Uz + (size_t)jb * H)
                                          : (Ur + (size_t)(jb - H) * H);
                gemm_tile_big<1>(&sh.b, i0, mtile, jb, B, (const float*)0, (float*)0);
            }
            grid_sync2(bid, nb, cnt);

            ntiles = pt64 * 4;
            for (int t = bid; t < ntiles; t += nb) {
                int pt = t >> 2;
                int jb = (t & 3) * 128;
                int i0 = ls + pt * 64;
                int mtile = Nl - pt * 64; if (mtile > 64) mtile = 64;
                gemm_tile_big<2>(&sh.b, i0, mtile, jb, Uh + (size_t)jb * H,
                                 (const float*)0, (float*)0);
            }
            grid_sync2(bid, nb, cnt);
        } else {
            // ---- mid-level 32x64 tile path ----
            int pt32 = (Nl + 31) >> 5;
            int ntiles = pt32 * 16;
            for (int t = bid; t < ntiles; t += nb) {
                int pt = t >> 4;
                int jbase = (t & 15) * 64;
                int i0 = ls + pt * 32;
                int mtile = Nl - pt * 32; if (mtile > 32) mtile = 32;
                wait_chunks(i0 >> 6, (i0 + mtile - 1) >> 6);
                gemm_tile<1>(&sh.s, i0, mtile, jbase, Uz, Ur, Uh);
            }
            grid_sync2(bid, nb, cnt);

            ntiles = pt32 * 8;
            for (int t = bid; t < ntiles; t += nb) {
                int pt = t >> 3;
                int jbase = (t & 7) * 64;
                int i0 = ls + pt * 32;
                int mtile = Nl - pt * 32; if (mtile > 32) mtile = 32;
                gemm_tile<2>(&sh.s, i0, mtile, jbase, Uz, Ur, Uh);
            }
            grid_sync2(bid, nb, cnt);
        }
    }
}

// ============================================================
__global__ void maxk_kernel() {
    int b = blockIdx.x;
    int rows_per = (NPAR + MAXB - 1) / MAXB;
    int r0 = b * rows_per;
    int r1 = min(NPAR, r0 + rows_per);
    for (int c = threadIdx.x; c < H; c += 256) {
        float m = -1e30f;
        for (int r = r0; r < r1; r++) m = fmaxf(m, g_ph[r * H + c]);
        g_pmax[b * H + c] = m;
    }
}

__global__ __launch_bounds__(512) void final_kernel(const float* __restrict__ Wout,
                                                    const float* __restrict__ bout,
                                                    float* __restrict__ out) {
    __shared__ float fin[H];
    __shared__ float logits[NCLASS];
    int tid = threadIdx.x;
    if (tid < H) {
        float m = -1e30f;
#pragma unroll 8
        for (int b = 0; b < MAXB; b++) m = fmaxf(m, g_pmax[b * H + tid]);
        fin[tid] = m;
    }
    __syncthreads();
    if (tid < NCLASS * 32) {
        int cls = tid >> 5, lane = tid & 31;
        float s = 0.f;
        for (int h = lane; h < H; h += 32) s += Wout[cls * H + h] * fin[h];
#pragma unroll
        for (int o = 16; o > 0; o >>= 1) s += __shfl_down_sync(0xffffffffu, s, o);
        if (lane == 0) logits[cls] = s + bout[cls];
    }
    __syncthreads();
    if (tid == 0) {
        float m = fmaxf(fmaxf(logits[0], logits[1]), fmaxf(logits[2], logits[3]));
        float e0 = expf(logits[0] - m), e1 = expf(logits[1] - m);
        float e2 = expf(logits[2] - m), e3 = expf(logits[3] - m);
        float inv = 1.0f / (e0 + e1 + e2 + e3);
        out[0] = e0 * inv; out[1] = e1 * inv; out[2] = e2 * inv; out[3] = e3 * inv;
    }
}

// ============================================================
extern "C" void kernel_launch(void* const* d_in, const int* in_sizes, int n_in,
                              void* d_out, int out_size) {
    const float* xw   = (const float*)d_in[0];
    const int*   xi   = (const int*)d_in[1];
    const int*   tree = (const int*)d_in[2];
    const float* E    = (const float*)d_in[3];
    const float* Wz   = (const float*)d_in[4];
    const float* Uz   = (const float*)d_in[5];
    const float* bz   = (const float*)d_in[6];
    const float* Wr   = (const float*)d_in[7];
    const float* Ur   = (const float*)d_in[8];
    const float* br   = (const float*)d_in[9];
    const float* Wh   = (const float*)d_in[10];
    const float* Uh   = (const float*)d_in[11];
    const float* bh   = (const float*)d_in[12];
    const float* Wout = (const float*)d_in[13];
    const float* bout = (const float*)d_in[14];

    cudaFuncSetAttribute(levels_kernel,
                         cudaFuncAttributeMaxDynamicSharedMemorySize, NPAR * 4 + 1024);
    int perSM = 0;
    cudaOccupancyMaxActiveBlocksPerMultiprocessor(&perSM, wave_kernel, 256, 0);
    if (perSM < 1) perSM = 1;
    if (perSM > 4) perSM = 4;
    int nsm = 0;
    cudaDeviceGetAttribute(&nsm, cudaDevAttrMultiProcessorCount, 0);
    if (nsm <= 0) nsm = 148;
    int grid = perSM * nsm;
    if (grid > MAXGRID) grid = MAXGRID;

    // gate blocks: up to 1/SM, at most a third of the grid
    int ngate = nsm;
    if (ngate > grid / 3) ngate = grid / 3;
    if (ngate < 1) ngate = 1;
    int nwave = grid - ngate;

    int rpb = (NROWS + nwave - 1) / nwave;
    int small_thresh = (rpb <= RPB_MAX) ? 96 : 0;

    dim3 pg((VOCAB + 31) / 32, H / 32);
    prep_kernel<<<pg, 256>>>(E);
    xe_kernel<<<NTOT, 128>>>(xw, xi);

    levels_kernel<<<1, 1024, NPAR * 4>>>(tree);
    wave_kernel<<<grid, 256>>>(tree, Uz, Ur, Uh, Wz, Wr, Wh, bz, br, bh,
                               nwave, small_thresh);

    maxk_kernel<<<MAXB, 256>>>();
    final_kernel<<<1, 512>>>(Wout, bout, (float*)d_out);
    (void)in_sizes; (void)n_in; (void)out_size;
}

// round 16
// speedup vs baseline: 1.1504x; 1.1504x over previous
#include <cuda_runtime.h>
#include <math.h>

#define H 512
#define HEADS 8
#define DK 64
#define NCLASS 4
#define VOCAB 5000
#define LW 32
#define NLEAF 20000
#define NPAR 20000
#define NTOT (NLEAF + NPAR)
#define DEG 4
#define NLAYER 5
#define MAXB 512
#define MAXL 512
#define MAXGRID 1024
#define NROWS 1536           // 512 Uz + 512 Ur + 512 Uh
#define RPB_MAX 8            // max U rows cached per block
#define BIGLVL 768           // Nl >= BIGLVL -> 64x128 tiles

// ---- static device scratch ----
__device__ float g_Et[VOCAB * H];
__device__ float g_xe[NTOT * H];
__device__ float g_gz[NPAR * H];   // Wz@xe+bz -> z after B1
__device__ float g_gr[NPAR * H];   // Wr@xe+br -> mem*r after B1
__device__ float g_gh[NPAR * H];   // Wh@xe+bh
__device__ float g_mem[NPAR * H];
__device__ float g_ph[NPAR * H];
__device__ float g_pmax[MAXB * H];

__device__ int g_lvl[NPAR];
__device__ int g_lstart[MAXL + 2];
__device__ int g_nlev;
__device__ int g_order[NPAR];

// flag-array barrier
__device__ volatile int g_arr[MAXGRID];

// ============================================================
// prep: coalesced transpose E_bu[H][VOCAB] -> g_Et[VOCAB][H]
// ============================================================
__global__ __launch_bounds__(256) void prep_kernel(const float* __restrict__ E_bu) {
    __shared__ float tile[32][33];
    int v0 = blockIdx.x * 32;
    int h0 = blockIdx.y * 32;
    int tx = threadIdx.x & 31;
    int ty = threadIdx.x >> 5;   // 0..7
#pragma unroll
    for (int rr = 0; rr < 4; rr++) {
        int h = h0 + ty + rr * 8;
        int v = v0 + tx;
        if (v < VOCAB) tile[ty + rr * 8][tx] = E_bu[h * VOCAB + v];
    }
    __syncthreads();
#pragma unroll
    for (int rr = 0; rr < 4; rr++) {
        int v = v0 + ty + rr * 8;
        if (v < VOCAB) g_Et[v * H + h0 + tx] = tile[tx][ty + rr * 8];
    }
}

// ============================================================
// xe for node range [base, base+count)
// ============================================================
__global__ __launch_bounds__(128) void xe_kernel(const float* __restrict__ xw,
                                                 const int* __restrict__ xi,
                                                 int base) {
    __shared__ float sw[LW];
    __shared__ int si[LW];
    int n = base + blockIdx.x;
    int t = threadIdx.x;
    if (t < LW) { sw[t] = xw[n * LW + t]; si[t] = xi[n * LW + t]; }
    __syncthreads();
    float4 acc = make_float4(0.f, 0.f, 0.f, 0.f);
#pragma unroll 8
    for (int l = 0; l < LW; l++) {
        float w = sw[l];
        const float4 e = *(const float4*)&g_Et[si[l] * H + t * 4];
        acc.x += w * e.x; acc.y += w * e.y; acc.z += w * e.z; acc.w += w * e.w;
    }
    *(float4*)&g_xe[n * H + t * 4] = acc;
}

// ============================================================
// W-GEMMs merged, 128x128 tile, DOUBLE-BUFFERED smem (1 sync/step)
// ============================================================
#define BM 128
#define BN 128
#define BK 16
__global__ __launch_bounds__(256, 2) void sgemm_nt3(const float* __restrict__ Wz,
                                                    const float* __restrict__ Wr,
                                                    const float* __restrict__ Wh,
                                                    const float* __restrict__ bz,
                                                    const float* __restrict__ br,
                                                    const float* __restrict__ bh) {
    const int M = NPAR;
    const float* A = g_xe + NLEAF * H;
    int which = blockIdx.z;
    const float* B = (which == 0) ? Wz : (which == 1) ? Wr : Wh;
    const float* bias = (which == 0) ? bz : (which == 1) ? br : bh;
    float* C = (which == 0) ? g_gz : (which == 1) ? g_gr : g_gh;
    __shared__ __align__(16) float As[2][BK][BM];
    __shared__ __align__(16) float Bs[2][BK][BN];
    int row0 = blockIdx.x * BM;
    int n0 = blockIdx.y * BN;
    int tid = threadIdx.x;
    int tr = tid >> 4, tc = tid & 15;

    int m0 = tid >> 2, kq = tid & 3;
    int ar0 = row0 + m0, ar1 = row0 + m0 + 64;
    bool g0 = ar0 < M, g1 = ar1 < M;
    const float* aptr0 = &A[(size_t)ar0 * H + kq * 4];
    const float* aptr1 = &A[(size_t)ar1 * H + kq * 4];
    const float* bptr0 = &B[(size_t)(n0 + m0) * H + kq * 4];
    const float* bptr1 = &B[(size_t)(n0 + m0 + 64) * H + kq * 4];

    float acc[8][8];
#pragma unroll
    for (int i = 0; i < 8; i++)
#pragma unroll
        for (int j = 0; j < 8; j++) acc[i][j] = 0.f;

    float4 pa0, pa1, pb0, pb1;
    const float4 z4 = make_float4(0.f, 0.f, 0.f, 0.f);

    pa0 = g0 ? *(const float4*)aptr0 : z4;
    pa1 = g1 ? *(const float4*)aptr1 : z4;
    pb0 = *(const float4*)bptr0;
    pb1 = *(const float4*)bptr1;
    {
        As[0][kq * 4 + 0][m0] = pa0.x; As[0][kq * 4 + 1][m0] = pa0.y;
        As[0][kq * 4 + 2][m0] = pa0.z; As[0][kq * 4 + 3][m0] = pa0.w;
        As[0][kq * 4 + 0][m0 + 64] = pa1.x; As[0][kq * 4 + 1][m0 + 64] = pa1.y;
        As[0][kq * 4 + 2][m0 + 64] = pa1.z; As[0][kq * 4 + 3][m0 + 64] = pa1.w;
        Bs[0][kq * 4 + 0][m0] = pb0.x; Bs[0][kq * 4 + 1][m0] = pb0.y;
        Bs[0][kq * 4 + 2][m0] = pb0.z; Bs[0][kq * 4 + 3][m0] = pb0.w;
        Bs[0][kq * 4 + 0][m0 + 64] = pb1.x; Bs[0][kq * 4 + 1][m0 + 64] = pb1.y;
        Bs[0][kq * 4 + 2][m0 + 64] = pb1.z; Bs[0][kq * 4 + 3][m0 + 64] = pb1.w;
    }
    __syncthreads();

    const int NSTEP = H / BK;   // 32
    for (int step = 0; step < NSTEP; step++) {
        int cur = step & 1;
        if (step < NSTEP - 1) {
            int off = (step + 1) * BK;
            pa0 = g0 ? *(const float4*)(aptr0 + off) : z4;
            pa1 = g1 ? *(const float4*)(aptr1 + off) : z4;
            pb0 = *(const float4*)(bptr0 + off);
            pb1 = *(const float4*)(bptr1 + off);
        }
#pragma unroll
        for (int kk = 0; kk < BK; kk++) {
            float ra[8], rb[8];
#pragma unroll
            for (int i = 0; i < 8; i++) ra[i] = As[cur][kk][tr * 8 + i];
#pragma unroll
            for (int j = 0; j < 8; j++) rb[j] = Bs[cur][kk][tc * 8 + j];
#pragma unroll
            for (int i = 0; i < 8; i++)
#pragma unroll
                for (int j = 0; j < 8; j++) acc[i][j] += ra[i] * rb[j];
        }
        if (step < NSTEP - 1) {
            int nxt = cur ^ 1;
            As[nxt][kq * 4 + 0][m0] = pa0.x; As[nxt][kq * 4 + 1][m0] = pa0.y;
            As[nxt][kq * 4 + 2][m0] = pa0.z; As[nxt][kq * 4 + 3][m0] = pa0.w;
            As[nxt][kq * 4 + 0][m0 + 64] = pa1.x; As[nxt][kq * 4 + 1][m0 + 64] = pa1.y;
            As[nxt][kq * 4 + 2][m0 + 64] = pa1.z; As[nxt][kq * 4 + 3][m0 + 64] = pa1.w;
            Bs[nxt][kq * 4 + 0][m0] = pb0.x; Bs[nxt][kq * 4 + 1][m0] = pb0.y;
            Bs[nxt][kq * 4 + 2][m0] = pb0.z; Bs[nxt][kq * 4 + 3][m0] = pb0.w;
            Bs[nxt][kq * 4 + 0][m0 + 64] = pb1.x; Bs[nxt][kq * 4 + 1][m0 + 64] = pb1.y;
            Bs[nxt][kq * 4 + 2][m0 + 64] = pb1.z; Bs[nxt][kq * 4 + 3][m0 + 64] = pb1.w;
            __syncthreads();
        }
    }

#pragma unroll
    for (int i = 0; i < 8; i++) {
        int row = row0 + tr * 8 + i;
        if (row >= M) continue;
#pragma unroll
        for (int j = 0; j < 8; j++) {
            int col = n0 + tc * 8 + j;
            C[row * H + col] = acc[i][j] + bias[col];
        }
    }
}

// ============================================================
// Levels + bucketing (+ barrier init). Single block, 1024 threads.
// ============================================================
extern __shared__ int s_dyn[];
__global__ void levels_kernel(const int* __restrict__ tree) {
    volatile int* lvl = s_dyn;
    int tid = threadIdx.x;
    int nt = blockDim.x;
    __shared__ int changed;
    __shared__ int s_maxl;
    __shared__ int cnt[MAXL + 1];

    if (tid < MAXGRID) g_arr[tid] = 0;

    for (int p = tid; p < NPAR; p += nt) lvl[p] = 1;
    if (tid == 0) s_maxl = 1;
    __syncthreads();

    for (int it = 0; it < 4096; it++) {
        if (tid == 0) changed = 0;
        __syncthreads();
        int ch = 0;
        for (int p = tid; p < NPAR; p += nt) {
            int4 t4 = ((const int4*)tree)[p];
            int m = 1;
            int c, v;
            c = t4.x; if (c >= NLEAF) { v = lvl[c - NLEAF] + 1; if (v > m) m = v; }
            c = t4.y; if (c >= NLEAF) { v = lvl[c - NLEAF] + 1; if (v > m) m = v; }
            c = t4.z; if (c >= NLEAF) { v = lvl[c - NLEAF] + 1; if (v > m) m = v; }
            c = t4.w; if (c >= NLEAF) { v = lvl[c - NLEAF] + 1; if (v > m) m = v; }
            if (m > lvl[p]) { lvl[p] = m; ch = 1; }
        }
        if (ch) changed = 1;
        __syncthreads();
        if (!changed) break;
    }

    for (int i = tid; i <= MAXL; i += nt) cnt[i] = 0;
    __syncthreads();
    int mymax = 1;
    for (int p = tid; p < NPAR; p += nt) {
        int l = lvl[p]; if (l > MAXL) l = MAXL;
        atomicAdd(&cnt[l], 1);
        if (l > mymax) mymax = l;
    }
    atomicMax(&s_maxl, mymax);
    __syncthreads();
    if (tid == 0) {
        int acc = 0;
        for (int l = 0; l <= MAXL; l++) { g_lstart[l] = acc; acc += cnt[l]; }
        g_lstart[MAXL + 1] = acc;
        g_nlev = s_maxl;
    }
    __syncthreads();
    for (int i = tid; i <= MAXL; i += nt) cnt[i] = g_lstart[i];
    __syncthreads();
    for (int p = tid; p < NPAR; p += nt) {
        int l = lvl[p]; if (l > MAXL) l = MAXL;
        int pos = atomicAdd(&cnt[l], 1);
        g_order[pos] = p;
        g_lvl[p] = l;
    }
}

// ============================================================
// Persistent wavefront kernel
// ============================================================
struct alignas(16) ShSmall {
    float As[16][32];
    float Bs[16][64];
    int pidx[32];
};
struct alignas(16) ShBig {
    float As[32][64];
    float Bs[32][128];
    int pidx[64];
};
union alignas(16) ShU { ShSmall s; ShBig b; };

// all-to-all flag barrier with tight-poll fast path
__device__ __forceinline__ void grid_sync2(int bid, int nb, int& cnt) {
    cnt++;
    __threadfence();
    __syncthreads();
    if (threadIdx.x == 0) g_arr[bid] = cnt;
    for (int i = threadIdx.x; i < nb; i += blockDim.x) {
        int tries = 0;
        while (g_arr[i] < cnt) {
            if (++tries > 64) __nanosleep(64);
        }
    }
    __threadfence();
    __syncthreads();
}

// ---- epilogue helper ----
template <int PHASE>
__device__ __forceinline__ void epilogue_elem(size_t pbase, int col, float v) {
    if (PHASE == 1) {
        if (col < H) {
            g_gz[pbase + col] = 1.0f / (1.0f + expf(-(v + g_gz[pbase + col])));
        } else {
            int c2 = col - H;
            float r = 1.0f / (1.0f + expf(-(v + g_gr[pbase + c2])));
            g_gr[pbase + c2] = g_mem[pbase + c2] * r;
        }
    } else {
        float cc = tanhf(v + g_gh[pbase + col]);
        float z = g_gz[pbase + col];
        float m = g_mem[pbase + col];
        g_ph[pbase + col] = z * m + (1.0f - z) * cc;
    }
}

// 32 x 64 output tile, full K=512, scalar FFMA (mid levels).
template <int PHASE>
__device__ void gemm_tile(ShSmall* sb, int i0, int mtile, int jbase,
                          const float* __restrict__ Uz,
                          const float* __restrict__ Ur,
                          const float* __restrict__ Uh) {
    int tid = threadIdx.x;
    if (tid < 32) sb->pidx[tid] = g_order[i0 + ((tid < mtile) ? tid : 0)];
    __syncthreads();

    const float* Asrc = (PHASE == 1) ? g_mem : g_gr;
    const float* Bsrc;
    if (PHASE == 1) Bsrc = (jbase < H) ? (Uz + (size_t)jbase * H)
                                       : (Ur + (size_t)(jbase - H) * H);
    else            Bsrc = Uh + (size_t)jbase * H;

    float acc[2][4];
#pragma unroll
    for (int a = 0; a < 2; a++)
#pragma unroll
        for (int b = 0; b < 4; b++) acc[a][b] = 0.f;

    int tr = tid >> 4, tc = tid & 15;

    for (int k0 = 0; k0 < H; k0 += 16) {
        if (tid < 128) {
            int row = tid >> 2, kq = tid & 3;
            float4 f = *(const float4*)&Asrc[(size_t)sb->pidx[row] * H + k0 + kq * 4];
            sb->As[kq * 4 + 0][row] = f.x; sb->As[kq * 4 + 1][row] = f.y;
            sb->As[kq * 4 + 2][row] = f.z; sb->As[kq * 4 + 3][row] = f.w;
        }
        {
            int nn = tid >> 2, kq = tid & 3;
            float4 f = *(const float4*)&Bsrc[(size_t)nn * H + k0 + kq * 4];
            sb->Bs[kq * 4 + 0][nn] = f.x; sb->Bs[kq * 4 + 1][nn] = f.y;
            sb->Bs[kq * 4 + 2][nn] = f.z; sb->Bs[kq * 4 + 3][nn] = f.w;
        }
        __syncthreads();
#pragma unroll
        for (int kk = 0; kk < 16; kk++) {
            float2 ra = *(const float2*)&sb->As[kk][tr * 2];
            float4 rb = *(const float4*)&sb->Bs[kk][tc * 4];
            acc[0][0] += ra.x * rb.x; acc[0][1] += ra.x * rb.y;
            acc[0][2] += ra.x * rb.z; acc[0][3] += ra.x * rb.w;
            acc[1][0] += ra.y * rb.x; acc[1][1] += ra.y * rb.y;
            acc[1][2] += ra.y * rb.z; acc[1][3] += ra.y * rb.w;
        }
        __syncthreads();
    }

#pragma unroll
    for (int a = 0; a < 2; a++) {
        int i = tr * 2 + a;
        if (i >= mtile) continue;
        size_t pbase = (size_t)sb->pidx[i] * H;
#pragma unroll
        for (int b = 0; b < 4; b++)
            epilogue_elem<PHASE>(pbase, jbase + tc * 4 + b, acc[a][b]);
    }
    __syncthreads();
}

// 64 x 128 output tile, K=512 in BK=32 chunks w/ register prefetch (big levels).
template <int PHASE>
__device__ void gemm_tile_big(ShBig* sb, int i0, int mtile, int jbase,
                              const float* __restrict__ Uz,
                              const float* __restrict__ Ur,
                              const float* __restrict__ Uh) {
    int tid = threadIdx.x;
    if (tid < 64) sb->pidx[tid] = g_order[i0 + ((tid < mtile) ? tid : 0)];
    __syncthreads();

    const float* Asrc = (PHASE == 1) ? g_mem : g_gr;
    const float* Bsrc;
    if (PHASE == 1) Bsrc = (jbase < H) ? (Uz + (size_t)jbase * H)
                                       : (Ur + (size_t)(jbase - H) * H);
    else            Bsrc = Uh + (size_t)jbase * H;

    float acc[4][8];
#pragma unroll
    for (int a = 0; a < 4; a++)
#pragma unroll
        for (int b = 0; b < 8; b++) acc[a][b] = 0.f;

    int tr = tid >> 4, tc = tid & 15;

    int kq = tid & 7;
    int arow0 = tid >> 3;
    int arow1 = arow0 + 32;
    const float* aptr0 = &Asrc[(size_t)sb->pidx[arow0] * H + kq * 4];
    const float* aptr1 = &Asrc[(size_t)sb->pidx[arow1] * H + kq * 4];
    const float* bptr0 = &Bsrc[(size_t)arow0 * H + kq * 4];
    const float* bptr1 = &Bsrc[(size_t)(arow0 + 32) * H + kq * 4];
    const float* bptr2 = &Bsrc[(size_t)(arow0 + 64) * H + kq * 4];
    const float* bptr3 = &Bsrc[(size_t)(arow0 + 96) * H + kq * 4];

    float4 rA0 = *(const float4*)aptr0;
    float4 rA1 = *(const float4*)aptr1;
    float4 rB0 = *(const float4*)bptr0;
    float4 rB1 = *(const float4*)bptr1;
    float4 rB2 = *(const float4*)bptr2;
    float4 rB3 = *(const float4*)bptr3;

    for (int c = 0; c < 16; c++) {
        __syncthreads();
        sb->As[kq * 4 + 0][arow0] = rA0.x; sb->As[kq * 4 + 1][arow0] = rA0.y;
        sb->As[kq * 4 + 2][arow0] = rA0.z; sb->As[kq * 4 + 3][arow0] = rA0.w;
        sb->As[kq * 4 + 0][arow1] = rA1.x; sb->As[kq * 4 + 1][arow1] = rA1.y;
        sb->As[kq * 4 + 2][arow1] = rA1.z; sb->As[kq * 4 + 3][arow1] = rA1.w;
        sb->Bs[kq * 4 + 0][arow0] = rB0.x; sb->Bs[kq * 4 + 1][arow0] = rB0.y;
        sb->Bs[kq * 4 + 2][arow0] = rB0.z; sb->Bs[kq * 4 + 3][arow0] = rB0.w;
        sb->Bs[kq * 4 + 0][arow0 + 32] = rB1.x; sb->Bs[kq * 4 + 1][arow0 + 32] = rB1.y;
        sb->Bs[kq * 4 + 2][arow0 + 32] = rB1.z; sb->Bs[kq * 4 + 3][arow0 + 32] = rB1.w;
        sb->Bs[kq * 4 + 0][arow0 + 64] = rB2.x; sb->Bs[kq * 4 + 1][arow0 + 64] = rB2.y;
        sb->Bs[kq * 4 + 2][arow0 + 64] = rB2.z; sb->Bs[kq * 4 + 3][arow0 + 64] = rB2.w;
        sb->Bs[kq * 4 + 0][arow0 + 96] = rB3.x; sb->Bs[kq * 4 + 1][arow0 + 96] = rB3.y;
        sb->Bs[kq * 4 + 2][arow0 + 96] = rB3.z; sb->Bs[kq * 4 + 3][arow0 + 96] = rB3.w;
        __syncthreads();
        if (c < 15) {
            int off = (c + 1) * 32;
            rA0 = *(const float4*)(aptr0 + off);
            rA1 = *(const float4*)(aptr1 + off);
            rB0 = *(const float4*)(bptr0 + off);
            rB1 = *(const float4*)(bptr1 + off);
            rB2 = *(const float4*)(bptr2 + off);
            rB3 = *(const float4*)(bptr3 + off);
        }
#pragma unroll
        for (int kk = 0; kk < 32; kk++) {
            float4 ra = *(const float4*)&sb->As[kk][tr * 4];
            float4 rb0 = *(const float4*)&sb->Bs[kk][tc * 8];
            float4 rb1 = *(const float4*)&sb->Bs[kk][tc * 8 + 4];
            float rav[4] = {ra.x, ra.y, ra.z, ra.w};
            float rbv[8] = {rb0.x, rb0.y, rb0.z, rb0.w, rb1.x, rb1.y, rb1.z, rb1.w};
#pragma unroll
            for (int a = 0; a < 4; a++)
#pragma unroll
                for (int b = 0; b < 8; b++) acc[a][b] += rav[a] * rbv[b];
        }
    }

#pragma unroll
    for (int a = 0; a < 4; a++) {
        int i = tr * 4 + a;
        if (i >= mtile) continue;
        size_t pbase = (size_t)sb->pidx[i] * H;
#pragma unroll
        for (int b = 0; b < 8; b++)
            epilogue_elem<PHASE>(pbase, jbase + tc * 8 + b, acc[a][b]);
    }
    __syncthreads();
}

// ============================================================
// Warp-level attention: one warp handles (parent p, 2 heads).
// ============================================================
__device__ __forceinline__ void warp_attn2(int p, int hpair, int lane,
                                           const int* __restrict__ tree) {
    int4 t4 = ((const int4*)tree)[p];
    int carr[DEG] = {t4.x, t4.y, t4.z, t4.w};
    int cidx[DEG];
    int nc = 0;
#pragma unroll
    for (int j = 0; j < DEG; j++) {
        int c = carr[j];
        if (c > -1) cidx[nc++] = c;
    }

    int hd = hpair * 2 + (lane >> 4);
    int w = lane & 15;
    int off = hd * DK + w * 4;

    float4 cur[DEG];
#pragma unroll
    for (int q = 0; q < DEG; q++) {
        if (q < nc) {
            int c = cidx[q];
            const float* src = (c < NLEAF) ? &g_xe[(size_t)c * H]
                                           : &g_ph[(size_t)(c - NLEAF) * H];
            cur[q] = *(const float4*)&src[off];
        } else {
            cur[q] = make_float4(0.f, 0.f, 0.f, 0.f);
        }
    }

#pragma unroll
    for (int layer = 0; layer < NLAYER; layer++) {
        float sc[DEG][DEG];
#pragma unroll
        for (int q = 0; q < DEG; q++) {
#pragma unroll
            for (int k = 0; k <= q; k++) {
                float s = cur[q].x * cur[k].x + cur[q].y * cur[k].y
                        + cur[q].z * cur[k].z + cur[q].w * cur[k].w;
#pragma unroll
                for (int o = 8; o > 0; o >>= 1)
                    s += __shfl_xor_sync(0xffffffffu, s, o);
                s *= 0.125f;
                sc[q][k] = s;
                sc[k][q] = s;
            }
        }
        float4 nxt[DEG];
#pragma unroll
        for (int q = 0; q < DEG; q++) {
            float m = -1e30f;
#pragma unroll
            for (int k = 0; k < DEG; k++) {
                float v = (k < nc) ? sc[q][k] : -1e30f;
                m = fmaxf(m, v);
            }
            float pk[DEG];
            float ssum = 0.f;
#pragma unroll
            for (int k = 0; k < DEG; k++) {
                float e = (k < nc) ? __expf(sc[q][k] - m) : 0.f;
                pk[k] = e;
                ssum += e;
            }
            float inv = 1.0f / ssum;
            float4 o = make_float4(0.f, 0.f, 0.f, 0.f);
#pragma unroll
            for (int k = 0; k < DEG; k++) {
                float wk = pk[k] * inv;
                o.x += wk * cur[k].x;
                o.y += wk * cur[k].y;
                o.z += wk * cur[k].z;
                o.w += wk * cur[k].w;
            }
            nxt[q] = o;
        }
#pragma unroll
        for (int q = 0; q < DEG; q++) cur[q] = nxt[q];
    }

    float4 mm = make_float4(0.f, 0.f, 0.f, 0.f);
#pragma unroll
    for (int q = 0; q < DEG; q++) {
        if (q < nc) {
            mm.x += cur[q].x; mm.y += cur[q].y;
            mm.z += cur[q].z; mm.w += cur[q].w;
        }
    }
    float invn = 1.0f / (float)nc;
    mm.x *= invn; mm.y *= invn; mm.z *= invn; mm.w *= invn;
    *(float4*)&g_mem[(size_t)p * H + off] = mm;
}

__global__ __launch_bounds__(256) void wave_kernel(const int* __restrict__ tree,
                                                   const float* __restrict__ Uz,
                                                   const float* __restrict__ Ur,
                                                   const float* __restrict__ Uh,
                                                   int small_thresh) {
    __shared__ ShU sh;
    __shared__ __align__(16) float uRows[RPB_MAX][H];
    int tid = threadIdx.x;
    int bid = blockIdx.x;
    int nb = gridDim.x;
    int wid = tid >> 5, lane = tid & 31;
    int nlev = g_nlev;
    int cnt = 0;

    int rpb = (NROWS + nb - 1) / nb;
    if (rpb > RPB_MAX) rpb = RPB_MAX;
    int myrow0 = bid * rpb;
    int mynrows = NROWS - myrow0;
    if (mynrows < 0) mynrows = 0;
    if (mynrows > rpb) mynrows = rpb;

    for (int rr = 0; rr < mynrows; rr++) {
        int R = myrow0 + rr;
        const float* src = (R < H) ? &Uz[(size_t)R * H]
                         : (R < 2 * H) ? &Ur[(size_t)(R - H) * H]
                         : &Uh[(size_t)(R - 2 * H) * H];
        if (tid < 128) ((float4*)uRows[rr])[tid] = ((const float4*)src)[tid];
    }
    __syncthreads();

    int gw = bid * 8 + wid;
    int ngw = nb * 8;

    for (int l = 1; l <= nlev; l++) {
        int ls = g_lstart[l];
        int le = g_lstart[l + 1];
        int Nl = le - ls;

        // ---- Phase A ----
        {
            int ntask = Nl * 4;
            for (int t = gw; t < ntask; t += ngw) {
                int pi = t >> 2;
                int hpair = t & 3;
                warp_attn2(g_order[ls + pi], hpair, lane, tree);
            }
        }
        grid_sync2(bid, nb, cnt);

        if (Nl <= small_thresh) {
            // ---- small-level GEMV path ----
            {
                int nzr = 0;
                int zr_rr[RPB_MAX];
                for (int rr = 0; rr < mynrows; rr++)
                    if (myrow0 + rr < 2 * H) zr_rr[nzr++] = rr;
                int ntask = nzr * Nl;
                for (int t = wid; t < ntask; t += 8) {
                    int ri = t / Nl;
                    int pi = t - ri * Nl;
                    int rr = zr_rr[ri];
                    int R = myrow0 + rr;
                    int p = g_order[ls + pi];
                    const float* mem = &g_mem[(size_t)p * H];
                    float s = 0.f;
#pragma unroll
                    for (int j = 0; j < 4; j++) {
                        int k = 4 * (lane + 32 * j);
                        float4 u = *(const float4*)&uRows[rr][k];
                        float4 m = *(const float4*)&mem[k];
                        s += u.x * m.x + u.y * m.y + u.z * m.z + u.w * m.w;
                    }
#pragma unroll
                    for (int o = 16; o > 0; o >>= 1) s += __shfl_down_sync(0xffffffffu, s, o);
                    if (lane == 0) {
                        if (R < H) {
                            size_t a = (size_t)p * H + R;
                            g_gz[a] = 1.0f / (1.0f + expf(-(s + g_gz[a])));
                        } else {
                            int r2 = R - H;
                            size_t a = (size_t)p * H + r2;
                            float r = 1.0f / (1.0f + expf(-(s + g_gr[a])));
                            g_gr[a] = mem[r2] * r;
                        }
                    }
                }
            }
            grid_sync2(bid, nb, cnt);

            {
                int ncr = 0;
                int c_rr[RPB_MAX];
                for (int rr = 0; rr < mynrows; rr++)
                    if (myrow0 + rr >= 2 * H) c_rr[ncr++] = rr;
                int ntask = ncr * Nl;
                for (int t = wid; t < ntask; t += 8) {
                    int ri = t / Nl;
                    int pi = t - ri * Nl;
                    int rr = c_rr[ri];
                    int row = myrow0 + rr - 2 * H;
                    int p = g_order[ls + pi];
                    const float* av = &g_gr[(size_t)p * H];
                    float s = 0.f;
#pragma unroll
                    for (int j = 0; j < 4; j++) {
                        int k = 4 * (lane + 32 * j);
                        float4 u = *(const float4*)&uRows[rr][k];
                        float4 m = *(const float4*)&av[k];
                        s += u.x * m.x + u.y * m.y + u.z * m.z + u.w * m.w;
                    }
#pragma unroll
                    for (int o = 16; o > 0; o >>= 1) s += __shfl_down_sync(0xffffffffu, s, o);
                    if (lane == 0) {
                        size_t a = (size_t)p * H + row;
                        float cc = tanhf(s + g_gh[a]);
                        float z = g_gz[a];
                        float m = g_mem[a];
                        g_ph[a] = z * m + (1.0f - z) * cc;
                    }
                }
            }
            grid_sync2(bid, nb, cnt);
        } else if (Nl >= BIGLVL) {
            // ---- big-level 64x128 tile path ----
            int pt64 = (Nl + 63) >> 6;
            int ntiles = pt64 * 8;
            for (int t = bid; t < ntiles; t += nb) {
                int pt = t >> 3;
                int jbase = (t & 7) * 128;
                int i0 = ls + pt * 64;
                int mtile = Nl - pt * 64; if (mtile > 64) mtile = 64;
                gemm_tile_big<1>(&sh.b, i0, mtile, jbase, Uz, Ur, Uh);
            }
            grid_sync2(bid, nb, cnt);

            ntiles = pt64 * 4;
            for (int t = bid; t < ntiles; t += nb) {
                int pt = t >> 2;
                int jbase = (t & 3) * 128;
                int i0 = ls + pt * 64;
                int mtile = Nl - pt * 64; if (mtile > 64) mtile = 64;
                gemm_tile_big<2>(&sh.b, i0, mtile, jbase, Uz, Ur, Uh);
            }
            grid_sync2(bid, nb, cnt);
        } else {
            // ---- mid-level 32x64 tile path ----
            int pt32 = (Nl + 31) >> 5;
            int ntiles = pt32 * 16;
            for (int t = bid; t < ntiles; t += nb) {
                int pt = t >> 4;
                int jbase = (t & 15) * 64;
                int i0 = ls + pt * 32;
                int mtile = Nl - pt * 32; if (mtile > 32) mtile = 32;
                gemm_tile<1>(&sh.s, i0, mtile, jbase, Uz, Ur, Uh);
            }
            grid_sync2(bid, nb, cnt);

            ntiles = pt32 * 8;
            for (int t = bid; t < ntiles; t += nb) {
                int pt = t >> 3;
                int jbase = (t & 7) * 64;
                int i0 = ls + pt * 32;
                int mtile = Nl - pt * 32; if (mtile > 32) mtile = 32;
                gemm_tile<2>(&sh.s, i0, mtile, jbase, Uz, Ur, Uh);
            }
            grid_sync2(bid, nb, cnt);
        }
    }
}

// ============================================================
__global__ void maxk_kernel() {
    int b = blockIdx.x;
    int rows_per = (NPAR + MAXB - 1) / MAXB;
    int r0 = b * rows_per;
    int r1 = min(NPAR, r0 + rows_per);
    for (int c = threadIdx.x; c < H; c += 256) {
        float m = -1e30f;
        for (int r = r0; r < r1; r++) m = fmaxf(m, g_ph[r * H + c]);
        g_pmax[b * H + c] = m;
    }
}

__global__ __launch_bounds__(512) void final_kernel(const float* __restrict__ Wout,
                                                    const float* __restrict__ bout,
                                                    float* __restrict__ out) {
    __shared__ float fin[H];
    __shared__ float logits[NCLASS];
    int tid = threadIdx.x;
    if (tid < H) {
        float m = -1e30f;
#pragma unroll 8
        for (int b = 0; b < MAXB; b++) m = fmaxf(m, g_pmax[b * H + tid]);
        fin[tid] = m;
    }
    __syncthreads();
    if (tid < NCLASS * 32) {
        int cls = tid >> 5, lane = tid & 31;
        float s = 0.f;
        for (int h = lane; h < H; h += 32) s += Wout[cls * H + h] * fin[h];
#pragma unroll
        for (int o = 16; o > 0; o >>= 1) s += __shfl_down_sync(0xffffffffu, s, o);
        if (lane == 0) logits[cls] = s + bout[cls];
    }
    __syncthreads();
    if (tid == 0) {
        float m = fmaxf(fmaxf(logits[0], logits[1]), fmaxf(logits[2], logits[3]));
        float e0 = expf(logits[0] - m), e1 = expf(logits[1] - m);
        float e2 = expf(logits[2] - m), e3 = expf(logits[3] - m);
        float inv = 1.0f / (e0 + e1 + e2 + e3);
        out[0] = e0 * inv; out[1] = e1 * inv; out[2] = e2 * inv; out[3] = e3 * inv;
    }
}

// ============================================================
extern "C" void kernel_launch(void* const* d_in, const int* in_sizes, int n_in,
                              void* d_out, int out_size) {
    const float* xw   = (const float*)d_in[0];
    const int*   xi   = (const int*)d_in[1];
    const int*   tree = (const int*)d_in[2];
    const float* E    = (const float*)d_in[3];
    const float* Wz   = (const float*)d_in[4];
    const float* Uz   = (const float*)d_in[5];
    const float* bz   = (const float*)d_in[6];
    const float* Wr   = (const float*)d_in[7];
    const float* Ur   = (const float*)d_in[8];
    const float* br   = (const float*)d_in[9];
    const float* Wh   = (const float*)d_in[10];
    const float* Uh   = (const float*)d_in[11];
    const float* bh   = (const float*)d_in[12];
    const float* Wout = (const float*)d_in[13];
    const float* bout = (const float*)d_in[14];

    // one-time resources (created on first, non-captured, call)
    static cudaStream_t s2 = 0;
    static cudaEvent_t evFork = 0, evJoin = 0;
    static bool inited = false;
    if (!inited) {
        cudaStreamCreateWithFlags(&s2, cudaStreamNonBlocking);
        cudaEventCreateWithFlags(&evFork, cudaEventDisableTiming);
        cudaEventCreateWithFlags(&evJoin, cudaEventDisableTiming);
        cudaFuncSetAttribute(levels_kernel,
                             cudaFuncAttributeMaxDynamicSharedMemorySize,
                             NPAR * 4 + 1024);
        inited = true;
    }

    int perSM = 0;
    cudaOccupancyMaxActiveBlocksPerMultiprocessor(&perSM, wave_kernel, 256, 0);
    if (perSM < 1) perSM = 1;
    if (perSM > 4) perSM = 4;
    int nsm = 0;
    cudaDeviceGetAttribute(&nsm, cudaDevAttrMultiProcessorCount, 0);
    if (nsm <= 0) nsm = 148;
    int grid = perSM * nsm;
    if (grid > MAXGRID) grid = MAXGRID;

    int rpb = (NROWS + grid - 1) / grid;
    int small_thresh = (rpb <= RPB_MAX) ? 96 : 0;

    // stream0: prep -> xe(parents) -> sgemm
    dim3 pg((VOCAB + 31) / 32, H / 32);
    prep_kernel<<<pg, 256>>>(E);

    // fork: stream2 runs xe(leaves) + levels concurrently with sgemm chain
    cudaEventRecord(evFork, 0);
    cudaStreamWaitEvent(s2, evFork, 0);

    xe_kernel<<<NPAR, 128>>>(xw, xi, NLEAF);          // parents (needed by sgemm)
    dim3 gg((NPAR + BM - 1) / BM, H / BN, 3);
    sgemm_nt3<<<gg, 256>>>(Wz, Wr, Wh, bz, br, bh);

    xe_kernel<<<NLEAF, 128, 0, s2>>>(xw, xi, 0);      // leaves (needed by wave)
    levels_kernel<<<1, 1024, NPAR * 4, s2>>>(tree);

    // join before wave
    cudaEventRecord(evJoin, s2);
    cudaStreamWaitEvent(0, evJoin, 0);

    wave_kernel<<<grid, 256>>>(tree, Uz, Ur, Uh, small_thresh);

    maxk_kernel<<<MAXB, 256>>>();
    final_kernel<<<1, 512>>>(Wout, bout, (float*)d_out);
    (void)in_sizes; (void)n_in; (void)out_size;
}